// round 8
// baseline (speedup 1.0000x reference)
#include <cuda_runtime.h>

// MyLossJC: loss = -0.5/B * sum_{b,i,k} log(0.5*(alpha[b,i] + beta[b,i,k] + eps))
//   S[b,i,k]  = sum over pixels p with target[b,p]==k of z[b,i,p]
//   cnt[b,k]  = #pixels with target==k
//   alpha     = S[b,i,i]/cnt[b,i]              (0 if cnt==0)
//   beta      = (cnt[b,k]-S[b,i,k])/cnt[b,k]   (0 if cnt==0)
//
// Single fused kernel: 1024 CTAs bin their tiles into g_S/g_cnt; the last
// CTA (ticket) computes the log-loss and restores all globals to zero so the
// captured graph is replayable. No separate zero/finalize launches.

#define NB 8
#define NC 19
#define HWQ (512 * 512)           // 262144 pixels per batch
#define CH 2048                   // pixels per CTA tile
#define CHUNKS_PER_B (HWQ / CH)   // 128 (power of two)
#define NCTAS (NB * CHUNKS_PER_B) // 1024
#define NTHREADS (NC * 32)        // 608: one warp per channel
#define PREF 8                    // float4 groups prefetched per batch

__device__ float g_S[NB * NC * NC];   // class-binned sums  (zero at load)
__device__ float g_cnt[NB * NC];      // class pixel counts (zero at load)
__device__ unsigned g_ticket;         // CTA completion counter (zero at load)

__global__ __launch_bounds__(NTHREADS, 1) void bin_kernel(
    const float* __restrict__ seg, const int* __restrict__ tgt,
    float* __restrict__ out)
{
    // bins[t][tid]: stride 608 is a multiple of 32 -> bank == lane id always,
    // so the dynamic-t accumulate is bank-conflict-free by construction.
    __shared__ float bins[NC * NTHREADS];           // 46208 B
    __shared__ unsigned tsm32[CH / 4];              // 2048 B (labels as bytes)
    __shared__ float red[NC];
    __shared__ unsigned is_last;

    int tid = threadIdx.x;
    int w = tid >> 5;        // warp id == channel id (0..18)
    int l = tid & 31;

    int b     = blockIdx.x >> 7;                 // CHUNKS_PER_B == 128
    int chunk = blockIdx.x & (CHUNKS_PER_B - 1);
    long p0   = (long)chunk * CH;

    #pragma unroll
    for (int t = 0; t < NC; t++) bins[t * NTHREADS + tid] = 0.0f;

    // Stage labels (int32 -> byte) into smem. No histogram atomics here;
    // counts are recomputed from the bytes in the flush phase.
    unsigned char* tsm = (unsigned char*)tsm32;
    const int* tb = tgt + (size_t)b * HWQ + p0;
    for (int j = tid; j < CH; j += NTHREADS) {
        int t = tb[j];
        t = (unsigned)t < NC ? t : 0;
        tsm[j] = (unsigned char)t;
    }
    __syncthreads();

    // Main loop: warp w sweeps channel w over the tile. PREF independent
    // LDG.128 issued before any smem RMW (MLP=PREF), all in registers.
    const float4* zb = (const float4*)(seg + ((size_t)b * NC + w) * HWQ + p0);
    float* binc = bins + tid;
    #pragma unroll 1
    for (int g = 0; g < CH / (128 * PREF); g++) {   // 2 batches of 8 groups
        float4   z[PREF];
        unsigned tt[PREF];
        #pragma unroll
        for (int u = 0; u < PREF; u++) {
            z[u]  = zb[(g * PREF + u) * 32 + l];
            tt[u] = tsm32[(g * PREF + u) * 32 + l];
        }
        #pragma unroll
        for (int u = 0; u < PREF; u++) {
            binc[((tt[u]      ) & 0xFF) * NTHREADS] += z[u].x;
            binc[((tt[u] >> 8 ) & 0xFF) * NTHREADS] += z[u].y;
            binc[((tt[u] >> 16) & 0xFF) * NTHREADS] += z[u].z;
            binc[((tt[u] >> 24)       ) * NTHREADS] += z[u].w;
        }
    }
    __syncthreads();

    // Flush S: 361 threads, each sums one (class t, channel w2) pair across
    // the 32 lane columns with a rotation stagger (bank-conflict-free).
    if (tid < NC * NC) {
        int t  = tid / NC;        // class k
        int w2 = tid - t * NC;    // channel i
        int l0 = tid & 31;
        const float* row = bins + t * NTHREADS + w2 * 32;
        float s = 0.0f;
        #pragma unroll
        for (int j = 0; j < 32; j++) s += row[(l0 + j) & 31];
        atomicAdd(&g_S[((size_t)b * NC + w2) * NC + t], s);
    }

    // Counts: warp w counts class-w bytes via SIMD byte-compare.
    {
        unsigned pat = w * 0x01010101u;
        int c = 0;
        #pragma unroll
        for (int j = 0; j < CH / 128; j++)
            c += __popc(__vcmpeq4(tsm32[j * 32 + l], pat));
        c >>= 3;                      // 0xFF per match -> 8 bits per match
        #pragma unroll
        for (int off = 16; off; off >>= 1)
            c += __shfl_xor_sync(0xFFFFFFFFu, c, off);
        if (l == 0) atomicAdd(&g_cnt[b * NC + w], (float)c);
    }

    // Last CTA: compute loss, write out, restore globals for next replay.
    __threadfence();
    __syncthreads();
    if (tid == 0) is_last = (atomicAdd(&g_ticket, 1u) == NCTAS - 1) ? 1u : 0u;
    __syncthreads();
    if (!is_last) return;

    const float eps = 2.2204460492503131e-16f;
    float acc = 0.0f;
    for (int idx = tid; idx < NB * NC * NC; idx += NTHREADS) {
        int bb = idx / (NC * NC);
        int r  = idx - bb * (NC * NC);
        int i  = r / NC;
        int k  = r - i * NC;
        float cnti = __ldcg(&g_cnt[bb * NC + i]);
        float cntk = __ldcg(&g_cnt[bb * NC + k]);
        float Sik  = __ldcg(&g_S[(bb * NC + i) * NC + k]);
        float Sii  = __ldcg(&g_S[(bb * NC + i) * NC + i]);
        float alpha = (cnti > 0.0f) ? Sii / cnti : 0.0f;
        float beta  = (cntk > 0.0f) ? (cntk - Sik) / cntk : 0.0f;
        acc += logf(0.5f * (alpha + beta + eps));
    }
    #pragma unroll
    for (int off = 16; off; off >>= 1)
        acc += __shfl_xor_sync(0xFFFFFFFFu, acc, off);
    if (l == 0) red[w] = acc;
    __syncthreads();

    // Restore globals to zero for the next graph replay.
    for (int idx = tid; idx < NB * NC * NC; idx += NTHREADS) g_S[idx] = 0.0f;
    if (tid < NB * NC) g_cnt[tid] = 0.0f;

    if (tid == 0) {
        float s = 0.0f;
        #pragma unroll
        for (int j = 0; j < NC; j++) s += red[j];
        out[0] = -0.5f * s / (float)NB;
        g_ticket = 0u;
    }
}

extern "C" void kernel_launch(void* const* d_in, const int* in_sizes, int n_in,
                              void* d_out, int out_size)
{
    const float* seg = (const float*)d_in[0];
    const int*   tgt = (const int*)d_in[1];
    float*       out = (float*)d_out;

    bin_kernel<<<NCTAS, NTHREADS>>>(seg, tgt, out);
}

// round 9
// speedup vs baseline: 1.2110x; 1.2110x over previous
#include <cuda_runtime.h>

// MyLossJC: loss = -0.5/B * sum_{b,i,k} log(0.5*(alpha[b,i] + beta[b,i,k] + eps))
//   S[b,i,k]  = sum over pixels p with target[b,p]==k of z[b,i,p]
//   cnt[b,k]  = #pixels with target==k
// Single fused kernel, cp.async-staged seg tiles (per-warp private 3-deep ring),
// conflict-free per-thread bin columns, last-CTA finalize + global restore.

#define NB 8
#define NC 19
#define HWQ (512 * 512)           // 262144 pixels per batch
#define CH 2048                   // pixels per CTA tile
#define CHUNKS_PER_B (HWQ / CH)   // 128
#define NCTAS (NB * CHUNKS_PER_B) // 1024
#define NTHREADS (NC * 32)        // 608: one warp per channel
#define SUB 256                   // pixels per pipeline sub-chunk (per channel)
#define NSUB (CH / SUB)           // 8
#define NSTAGE 3                  // ring depth

struct SmemLayout {
    float    bins[NC * NTHREADS];         // 46208 B, stride 608 (mult of 32)
    unsigned tsm32[CH / 4];               // 2048 B: labels as bytes
    float    stage[NSTAGE][NC][SUB];      // 58368 B: cp.async ring
    float    red[NC];
    unsigned is_last;
};

__device__ float    g_S[NB * NC * NC];    // zero at module load
__device__ float    g_cnt[NB * NC];       // zero at module load
__device__ unsigned g_ticket;             // zero at module load

__device__ __forceinline__ void cp16(float* dst, const float* src) {
    unsigned d = (unsigned)__cvta_generic_to_shared(dst);
    asm volatile("cp.async.cg.shared.global [%0], [%1], 16;" :: "r"(d), "l"(src));
}
#define CP_COMMIT() asm volatile("cp.async.commit_group;" ::: "memory")
#define CP_WAIT(n)  asm volatile("cp.async.wait_group %0;" :: "n"(n) : "memory")

__global__ __launch_bounds__(NTHREADS, 2) void bin_kernel(
    const float* __restrict__ seg, const int* __restrict__ tgt,
    float* __restrict__ out)
{
    extern __shared__ char smem_raw[];
    SmemLayout* sm = (SmemLayout*)smem_raw;

    int tid = threadIdx.x;
    int w = tid >> 5;        // warp id == channel id (0..18)
    int l = tid & 31;

    int b     = blockIdx.x >> 7;                 // CHUNKS_PER_B == 128
    int chunk = blockIdx.x & (CHUNKS_PER_B - 1);
    long p0   = (long)chunk * CH;

    // Kick off the first NSTAGE sub-chunk copies for this warp's channel
    // before anything else; labels + bin zeroing overlap the DRAM latency.
    const float* gsrc = seg + ((size_t)b * NC + w) * HWQ + p0;
    #pragma unroll
    for (int s = 0; s < NSTAGE; s++) {
        float* dst = &sm->stage[s][w][0];
        const float* src = gsrc + s * SUB;
        cp16(dst + (0 * 32 + l) * 4, src + (0 * 32 + l) * 4);
        cp16(dst + (1 * 32 + l) * 4, src + (1 * 32 + l) * 4);
        CP_COMMIT();
    }

    #pragma unroll
    for (int t = 0; t < NC; t++) sm->bins[t * NTHREADS + tid] = 0.0f;

    // Stage labels (int32 -> byte) into smem.
    {
        unsigned char* tsm = (unsigned char*)sm->tsm32;
        const int* tb = tgt + (size_t)b * HWQ + p0;
        for (int j = tid; j < CH; j += NTHREADS) {
            int t = tb[j];
            t = (unsigned)t < NC ? t : 0;
            tsm[j] = (unsigned char)t;
        }
    }
    __syncthreads();

    // Pipelined main loop: wait for sub-chunk s, consume it from smem,
    // refill the ring slot with sub-chunk s+NSTAGE. Per-warp private ring,
    // no cross-warp synchronization needed.
    float* binc = sm->bins + tid;
    #pragma unroll 1
    for (int s = 0; s < NSUB; s++) {
        CP_WAIT(NSTAGE - 1);                     // sub-chunk s landed
        const float4*   z4  = (const float4*)&sm->stage[s % NSTAGE][w][0];
        const unsigned* tls = sm->tsm32 + s * (SUB / 4);
        #pragma unroll
        for (int j = 0; j < SUB / 128; j++) {    // 2
            float4   z  = z4[j * 32 + l];
            unsigned tt = tls[j * 32 + l];
            binc[((tt      ) & 0xFF) * NTHREADS] += z.x;
            binc[((tt >> 8 ) & 0xFF) * NTHREADS] += z.y;
            binc[((tt >> 16) & 0xFF) * NTHREADS] += z.z;
            binc[((tt >> 24)       ) * NTHREADS] += z.w;
        }
        int nxt = s + NSTAGE;
        if (nxt < NSUB) {
            float* dst = &sm->stage[nxt % NSTAGE][w][0];
            const float* src = gsrc + nxt * SUB;
            cp16(dst + (0 * 32 + l) * 4, src + (0 * 32 + l) * 4);
            cp16(dst + (1 * 32 + l) * 4, src + (1 * 32 + l) * 4);
        }
        CP_COMMIT();                             // keep group count uniform
    }
    __syncthreads();

    // Flush S: 361 threads, each sums one (class t, channel w2) pair across
    // the 32 lane columns with a rotation stagger (bank-conflict-free).
    if (tid < NC * NC) {
        int t  = tid / NC;        // class k
        int w2 = tid - t * NC;    // channel i
        int l0 = tid & 31;
        const float* row = sm->bins + t * NTHREADS + w2 * 32;
        float s = 0.0f;
        #pragma unroll
        for (int j = 0; j < 32; j++) s += row[(l0 + j) & 31];
        atomicAdd(&g_S[((size_t)b * NC + w2) * NC + t], s);
    }

    // Counts: warp w counts class-w bytes via SIMD byte-compare.
    {
        unsigned pat = w * 0x01010101u;
        int c = 0;
        #pragma unroll
        for (int j = 0; j < CH / 128; j++)
            c += __popc(__vcmpeq4(sm->tsm32[j * 32 + l], pat));
        c >>= 3;                      // 0xFF per match -> 8 bits per match
        #pragma unroll
        for (int off = 16; off; off >>= 1)
            c += __shfl_xor_sync(0xFFFFFFFFu, c, off);
        if (l == 0) atomicAdd(&g_cnt[b * NC + w], (float)c);
    }

    // Last CTA: compute loss, write out, restore globals for next replay.
    __threadfence();
    __syncthreads();
    if (tid == 0) sm->is_last = (atomicAdd(&g_ticket, 1u) == NCTAS - 1) ? 1u : 0u;
    __syncthreads();
    if (!sm->is_last) return;

    const float eps = 2.2204460492503131e-16f;
    float acc = 0.0f;
    for (int idx = tid; idx < NB * NC * NC; idx += NTHREADS) {
        int bb = idx / (NC * NC);
        int r  = idx - bb * (NC * NC);
        int i  = r / NC;
        int k  = r - i * NC;
        float cnti = __ldcg(&g_cnt[bb * NC + i]);
        float cntk = __ldcg(&g_cnt[bb * NC + k]);
        float Sik  = __ldcg(&g_S[(bb * NC + i) * NC + k]);
        float Sii  = __ldcg(&g_S[(bb * NC + i) * NC + i]);
        float alpha = (cnti > 0.0f) ? Sii / cnti : 0.0f;
        float beta  = (cntk > 0.0f) ? (cntk - Sik) / cntk : 0.0f;
        acc += logf(0.5f * (alpha + beta + eps));
    }
    #pragma unroll
    for (int off = 16; off; off >>= 1)
        acc += __shfl_xor_sync(0xFFFFFFFFu, acc, off);
    if (l == 0) sm->red[w] = acc;
    __syncthreads();

    // Restore globals to zero for the next graph replay.
    for (int idx = tid; idx < NB * NC * NC; idx += NTHREADS) g_S[idx] = 0.0f;
    if (tid < NB * NC) g_cnt[tid] = 0.0f;

    if (tid == 0) {
        float s = 0.0f;
        #pragma unroll
        for (int j = 0; j < NC; j++) s += sm->red[j];
        out[0] = -0.5f * s / (float)NB;
        g_ticket = 0u;
    }
}

extern "C" void kernel_launch(void* const* d_in, const int* in_sizes, int n_in,
                              void* d_out, int out_size)
{
    const float* seg = (const float*)d_in[0];
    const int*   tgt = (const int*)d_in[1];
    float*       out = (float*)d_out;

    static int configured = 0;
    if (!configured) {
        cudaFuncSetAttribute(bin_kernel,
                             cudaFuncAttributeMaxDynamicSharedMemorySize,
                             (int)sizeof(SmemLayout));
        configured = 1;
    }
    bin_kernel<<<NCTAS, NTHREADS, sizeof(SmemLayout)>>>(seg, tgt, out);
}